// round 2
// baseline (speedup 1.0000x reference)
#include <cuda_runtime.h>

#define BB 8
#define CC 256
#define TT 2048
#define RR 32

// Scratch (allocation-free rule: __device__ globals)
__device__ float g_Q[BB*RR*TT];   // [b][r][t]
__device__ float g_K[BB*RR*TT];   // [b][r][t]
__device__ float g_V[BB*CC*TT];   // [b][c][t]

// ---------------------------------------------------------------------------
// Kernel 1: fused projections.  Treat [Wq;Wk;Wv] as a 320x256 weight matrix.
// Grid: (T/128, 5 row-groups, B).  Each CTA: 64 rows x 128 cols, reg-blocked.
// ---------------------------------------------------------------------------
__global__ __launch_bounds__(256) void proj_kernel(
    const float* __restrict__ x,
    const float* __restrict__ Wq, const float* __restrict__ bq,
    const float* __restrict__ Wk, const float* __restrict__ bk,
    const float* __restrict__ Wv, const float* __restrict__ bv)
{
    const int b   = blockIdx.z;
    const int g   = blockIdx.y;          // 0: q(32)+k(32) rows, 1..4: v rows
    const int t0  = blockIdx.x * 128;
    const int tid = threadIdx.x;

    __shared__ float w_s[64*33];
    __shared__ float x_s[32*132];

    float acc[4][8];
    #pragma unroll
    for (int i = 0; i < 4; i++)
        #pragma unroll
        for (int j = 0; j < 8; j++) acc[i][j] = 0.f;

    const int ty = tid >> 4, tx = tid & 15;

    for (int cc = 0; cc < CC; cc += 32) {
        // 64x32 weight chunk
        for (int i = tid; i < 64*32; i += 256) {
            int r = i >> 5, c = i & 31;
            float wv;
            if (g == 0) {
                wv = (r < 32) ? Wq[r*CC + cc + c] : Wk[(r-32)*CC + cc + c];
            } else {
                wv = Wv[((g-1)*64 + r)*CC + cc + c];
            }
            w_s[r*33 + c] = wv;
        }
        // 32x128 x chunk (float4, coalesced over t)
        for (int i = tid; i < 32*32; i += 256) {
            int c = i >> 5, tq = i & 31;
            float4 xv = *reinterpret_cast<const float4*>(&x[(b*CC + cc + c)*TT + t0 + tq*4]);
            *reinterpret_cast<float4*>(&x_s[c*132 + tq*4]) = xv;
        }
        __syncthreads();
        #pragma unroll
        for (int c = 0; c < 32; c++) {
            float wr[4], xr[8];
            #pragma unroll
            for (int i = 0; i < 4; i++) wr[i] = w_s[(ty*4+i)*33 + c];
            #pragma unroll
            for (int j = 0; j < 8; j++) xr[j] = x_s[c*132 + tx*8 + j];
            #pragma unroll
            for (int i = 0; i < 4; i++)
                #pragma unroll
                for (int j = 0; j < 8; j++)
                    acc[i][j] += wr[i] * xr[j];
        }
        __syncthreads();
    }

    #pragma unroll
    for (int i = 0; i < 4; i++) {
        int r = ty*4 + i;
        float bias; float* dst;
        if (g == 0) {
            if (r < 32) { bias = bq[r];    dst = &g_Q[(b*RR + r   )*TT]; }
            else        { bias = bk[r-32]; dst = &g_K[(b*RR + r-32)*TT]; }
        } else {
            int vr = (g-1)*64 + r;
            bias = bv[vr]; dst = &g_V[(b*CC + vr)*TT];
        }
        #pragma unroll
        for (int jj = 0; jj < 2; jj++) {
            float4 o;
            o.x = acc[i][jj*4+0] + bias; o.y = acc[i][jj*4+1] + bias;
            o.z = acc[i][jj*4+2] + bias; o.w = acc[i][jj*4+3] + bias;
            *reinterpret_cast<float4*>(&dst[t0 + tx*8 + jj*4]) = o;
        }
    }
}

// ---------------------------------------------------------------------------
// Kernel 2: flash attention, fp32 SIMT, online softmax.
// Grid: (T/64 row tiles, B).  256 threads, 2 CTAs/SM.
// Per 64-wide s-tile: S = q@k (4x4 per thread), softmax (4 threads/row),
// O += P@V (4t x 16c per thread, c strided by 16 for conflict-free v_s reads).
// ---------------------------------------------------------------------------
#define BM 64
#define BN 64
#define QS_PAD 33
#define KS_PAD 68
#define VS_PAD 65
#define SS_PAD 68
#define ATTN_SMEM_FLOATS (BM*QS_PAD + RR*KS_PAD + CC*VS_PAD + BM*SS_PAD + 3*BM)

__global__ __launch_bounds__(256, 2) void attn_kernel(
    const float* __restrict__ x, const float* __restrict__ gamma,
    float* __restrict__ out)
{
    extern __shared__ float sm[];
    float* q_s = sm;                      // [64][33]  q_s[t][r]
    float* k_s = q_s + BM*QS_PAD;         // [32][68]  k_s[r][s]
    float* v_s = k_s + RR*KS_PAD;         // [256][65] v_s[c][s]
    float* s_s = v_s + CC*VS_PAD;         // [64][68]  scores/probs
    float* m_s = s_s + BM*SS_PAD;         // [64] running max
    float* l_s = m_s + BM;                // [64] running sum
    float* a_s = l_s + BM;                // [64] rescale alpha

    const int b   = blockIdx.y;
    const int t0  = blockIdx.x * BM;
    const int tid = threadIdx.x;

    // q tile: coalesced over t, conflict-free strided smem stores
    for (int i = tid; i < BM*RR; i += 256) {
        int r = i >> 6, ttt = i & 63;
        q_s[ttt*QS_PAD + r] = g_Q[(b*RR + r)*TT + t0 + ttt];
    }
    if (tid < BM) { m_s[tid] = -1e30f; l_s[tid] = 0.f; }

    float acc[4][16];
    #pragma unroll
    for (int i = 0; i < 4; i++)
        #pragma unroll
        for (int j = 0; j < 16; j++) acc[i][j] = 0.f;

    const int tw   = tid >> 4, sx = tid & 15;   // S-phase & O-phase map
    const int row  = tid >> 2, part = tid & 3;  // softmax map

    for (int s0 = 0; s0 < TT; s0 += BN) {
        __syncthreads();   // protects k_s/v_s/s_s vs previous iter readers
        // K tile [32][64]
        for (int i = tid; i < RR*(BN/4); i += 256) {
            int r = i >> 4, sq = i & 15;
            float4 kv = *reinterpret_cast<const float4*>(&g_K[(b*RR + r)*TT + s0 + sq*4]);
            *reinterpret_cast<float4*>(&k_s[r*KS_PAD + sq*4]) = kv;
        }
        // V tile [256][64] (float4 gmem, scalar smem stores -> odd pad)
        for (int i = tid; i < CC*(BN/4); i += 256) {
            int c = i >> 4, sq = i & 15;
            float4 vv = *reinterpret_cast<const float4*>(&g_V[(b*CC + c)*TT + s0 + sq*4]);
            float* vp = &v_s[c*VS_PAD + sq*4];
            vp[0] = vv.x; vp[1] = vv.y; vp[2] = vv.z; vp[3] = vv.w;
        }
        __syncthreads();

        // S = q @ k : thread -> 4 t x 4 s
        {
            float sa[4][4];
            #pragma unroll
            for (int i = 0; i < 4; i++)
                #pragma unroll
                for (int j = 0; j < 4; j++) sa[i][j] = 0.f;
            #pragma unroll
            for (int r = 0; r < RR; r++) {
                float qv[4];
                #pragma unroll
                for (int i = 0; i < 4; i++) qv[i] = q_s[(tw*4+i)*QS_PAD + r];
                float4 kv = *reinterpret_cast<float4*>(&k_s[r*KS_PAD + sx*4]);
                #pragma unroll
                for (int i = 0; i < 4; i++) {
                    sa[i][0] += qv[i]*kv.x; sa[i][1] += qv[i]*kv.y;
                    sa[i][2] += qv[i]*kv.z; sa[i][3] += qv[i]*kv.w;
                }
            }
            #pragma unroll
            for (int i = 0; i < 4; i++) {
                float4 o; o.x = sa[i][0]; o.y = sa[i][1]; o.z = sa[i][2]; o.w = sa[i][3];
                *reinterpret_cast<float4*>(&s_s[(tw*4+i)*SS_PAD + sx*4]) = o;
            }
        }
        __syncthreads();

        // online softmax: 4 threads per row, shfl-combine
        {
            float* sr = &s_s[row*SS_PAD + part*16];
            float lmax = -1e30f;
            #pragma unroll
            for (int i = 0; i < 16; i++) lmax = fmaxf(lmax, sr[i]);
            lmax = fmaxf(lmax, __shfl_xor_sync(0xffffffffu, lmax, 1));
            lmax = fmaxf(lmax, __shfl_xor_sync(0xffffffffu, lmax, 2));
            float m_old = m_s[row];
            float m_new = fmaxf(m_old, lmax);
            float lsum = 0.f;
            #pragma unroll
            for (int i = 0; i < 16; i++) {
                float p = __expf(sr[i] - m_new);
                sr[i] = p; lsum += p;
            }
            lsum += __shfl_xor_sync(0xffffffffu, lsum, 1);
            lsum += __shfl_xor_sync(0xffffffffu, lsum, 2);
            if (part == 0) {
                float alpha = __expf(m_old - m_new);
                a_s[row] = alpha;
                l_s[row] = l_s[row]*alpha + lsum;
                m_s[row] = m_new;
            }
        }
        __syncthreads();

        // O = alpha*O + P @ V : thread -> 4 t x 16 c (c = sx + 16j)
        {
            float al[4];
            #pragma unroll
            for (int i = 0; i < 4; i++) al[i] = a_s[tw*4+i];
            #pragma unroll
            for (int i = 0; i < 4; i++)
                #pragma unroll
                for (int j = 0; j < 16; j++) acc[i][j] *= al[i];
            #pragma unroll 2
            for (int s = 0; s < BN; s++) {
                float pv[4];
                #pragma unroll
                for (int i = 0; i < 4; i++) pv[i] = s_s[(tw*4+i)*SS_PAD + s];
                #pragma unroll
                for (int j = 0; j < 16; j++) {
                    float vv = v_s[(sx + 16*j)*VS_PAD + s];
                    #pragma unroll
                    for (int i = 0; i < 4; i++) acc[i][j] += pv[i]*vv;
                }
            }
        }
    }
    __syncthreads();

    // epilogue: y[b][c][t] = x + gamma * O/l
    const float gm = gamma[0];
    float inv[4];
    #pragma unroll
    for (int i = 0; i < 4; i++) inv[i] = 1.0f / l_s[tw*4+i];
    #pragma unroll
    for (int j = 0; j < 16; j++) {
        int c = sx + 16*j;
        size_t gi = ((size_t)(b*CC + c))*TT + t0 + tw*4;
        float4 xv = *reinterpret_cast<const float4*>(&x[gi]);
        float4 o;
        o.x = xv.x + gm*acc[0][j]*inv[0];
        o.y = xv.y + gm*acc[1][j]*inv[1];
        o.z = xv.z + gm*acc[2][j]*inv[2];
        o.w = xv.w + gm*acc[3][j]*inv[3];
        *reinterpret_cast<float4*>(&out[gi]) = o;
    }
}

// ---------------------------------------------------------------------------
extern "C" void kernel_launch(void* const* d_in, const int* in_sizes, int n_in,
                              void* d_out, int out_size) {
    const float* x     = (const float*)d_in[0];
    const float* Wq    = (const float*)d_in[1];
    const float* bq    = (const float*)d_in[2];
    const float* Wk    = (const float*)d_in[3];
    const float* bk    = (const float*)d_in[4];
    const float* Wv    = (const float*)d_in[5];
    const float* bv    = (const float*)d_in[6];
    const float* gamma = (const float*)d_in[7];
    float* out = (float*)d_out;

    (void)in_sizes; (void)n_in; (void)out_size;

    // >48KB dynamic smem opt-in (idempotent, called every launch)
    cudaFuncSetAttribute(attn_kernel, cudaFuncAttributeMaxDynamicSharedMemorySize,
                         ATTN_SMEM_FLOATS * (int)sizeof(float));

    dim3 g1(TT/128, 5, BB);
    proj_kernel<<<g1, 256>>>(x, Wq, bq, Wk, bk, Wv, bv);

    dim3 g2(TT/BM, BB);
    attn_kernel<<<g2, 256, ATTN_SMEM_FLOATS * sizeof(float)>>>(x, gamma, out);
}

// round 3
// speedup vs baseline: 2.1887x; 2.1887x over previous
#include <cuda_runtime.h>
#include <cstdint>

#define BB 8
#define CC 256
#define TT 2048
#define RR 32

// Scratch (allocation-free rule: __device__ globals)
__device__ float g_Q[BB*RR*TT];   // [b][r][t]
__device__ float g_K[BB*RR*TT];   // [b][r][t]
__device__ float g_V[BB*CC*TT];   // [b][c][t]

// ---------------------------------------------------------------------------
// Kernel 1: fused projections (fp32 SIMT, unchanged this round).
// ---------------------------------------------------------------------------
__global__ __launch_bounds__(256) void proj_kernel(
    const float* __restrict__ x,
    const float* __restrict__ Wq, const float* __restrict__ bq,
    const float* __restrict__ Wk, const float* __restrict__ bk,
    const float* __restrict__ Wv, const float* __restrict__ bv)
{
    const int b   = blockIdx.z;
    const int g   = blockIdx.y;          // 0: q(32)+k(32) rows, 1..4: v rows
    const int t0  = blockIdx.x * 128;
    const int tid = threadIdx.x;

    __shared__ float w_s[64*33];
    __shared__ float x_s[32*132];

    float acc[4][8];
    #pragma unroll
    for (int i = 0; i < 4; i++)
        #pragma unroll
        for (int j = 0; j < 8; j++) acc[i][j] = 0.f;

    const int ty = tid >> 4, tx = tid & 15;

    for (int cc = 0; cc < CC; cc += 32) {
        for (int i = tid; i < 64*32; i += 256) {
            int r = i >> 5, c = i & 31;
            float wv;
            if (g == 0) {
                wv = (r < 32) ? Wq[r*CC + cc + c] : Wk[(r-32)*CC + cc + c];
            } else {
                wv = Wv[((g-1)*64 + r)*CC + cc + c];
            }
            w_s[r*33 + c] = wv;
        }
        for (int i = tid; i < 32*32; i += 256) {
            int c = i >> 5, tq = i & 31;
            float4 xv = *reinterpret_cast<const float4*>(&x[(b*CC + cc + c)*TT + t0 + tq*4]);
            *reinterpret_cast<float4*>(&x_s[c*132 + tq*4]) = xv;
        }
        __syncthreads();
        #pragma unroll
        for (int c = 0; c < 32; c++) {
            float wr[4], xr[8];
            #pragma unroll
            for (int i = 0; i < 4; i++) wr[i] = w_s[(ty*4+i)*33 + c];
            #pragma unroll
            for (int j = 0; j < 8; j++) xr[j] = x_s[c*132 + tx*8 + j];
            #pragma unroll
            for (int i = 0; i < 4; i++)
                #pragma unroll
                for (int j = 0; j < 8; j++)
                    acc[i][j] += wr[i] * xr[j];
        }
        __syncthreads();
    }

    #pragma unroll
    for (int i = 0; i < 4; i++) {
        int r = ty*4 + i;
        float bias; float* dst;
        if (g == 0) {
            if (r < 32) { bias = bq[r];    dst = &g_Q[(b*RR + r   )*TT]; }
            else        { bias = bk[r-32]; dst = &g_K[(b*RR + r-32)*TT]; }
        } else {
            int vr = (g-1)*64 + r;
            bias = bv[vr]; dst = &g_V[(b*CC + vr)*TT];
        }
        #pragma unroll
        for (int jj = 0; jj < 2; jj++) {
            float4 o;
            o.x = acc[i][jj*4+0] + bias; o.y = acc[i][jj*4+1] + bias;
            o.z = acc[i][jj*4+2] + bias; o.w = acc[i][jj*4+3] + bias;
            *reinterpret_cast<float4*>(&dst[t0 + tx*8 + jj*4]) = o;
        }
    }
}

// ---------------------------------------------------------------------------
// Kernel 2: flash attention with tf32 mma.sync (m16n8k8).
// Grid: (T/64, B).  256 threads = 8 warps, 2 CTAs/SM.
// Warp S-tile: m16 x n32.  Warp O-tile: m16 x n128 (64 fp32 acc regs).
// ---------------------------------------------------------------------------
#define BM 64
#define BN 64
#define QP 36
#define KP 72
#define VP 68
#define SP 68
#define SM_K (BM*QP)
#define SM_V (SM_K + RR*KP)
#define SM_S (SM_V + CC*VP)
#define SM_M (SM_S + BM*SP)
#define ATTN_SMEM_FLOATS (SM_M + 3*BM)

__device__ __forceinline__ void mma8(float* d,
    uint32_t a0, uint32_t a1, uint32_t a2, uint32_t a3,
    uint32_t b0, uint32_t b1)
{
    asm volatile(
        "mma.sync.aligned.m16n8k8.row.col.f32.tf32.tf32.f32 "
        "{%0,%1,%2,%3}, {%4,%5,%6,%7}, {%8,%9}, {%0,%1,%2,%3};"
        : "+f"(d[0]), "+f"(d[1]), "+f"(d[2]), "+f"(d[3])
        : "r"(a0), "r"(a1), "r"(a2), "r"(a3), "r"(b0), "r"(b1));
}

__device__ __forceinline__ uint32_t fbits(float f) { return __float_as_uint(f); }

__global__ __launch_bounds__(256, 2) void attn_kernel(
    const float* __restrict__ x, const float* __restrict__ gamma,
    float* __restrict__ out)
{
    extern __shared__ float sm[];
    float* q_s = sm;                 // [64][36]  q_s[t][r]
    float* k_s = sm + SM_K;          // [32][72]  k_s[r][s]
    float* v_s = sm + SM_V;          // [256][68] v_s[c][s]
    float* s_s = sm + SM_S;          // [64][68]  scores / probs
    float* m_s = sm + SM_M;          // [64]
    float* l_s = m_s + BM;           // [64]
    float* a_s = l_s + BM;           // [64]

    const int b    = blockIdx.y;
    const int t0   = blockIdx.x * BM;
    const int tid  = threadIdx.x;
    const int wid  = tid >> 5;
    const int lane = tid & 31;
    const int lq   = lane >> 2;      // 0..7
    const int lr   = lane & 3;       // 0..3
    const int mi   = wid >> 1;       // 0..3 -> 16-row chunk
    const int ni   = wid & 1;        // 0..1
    const int mrow = mi*16 + lq;     // this thread's first m row (and mrow+8)
    const int nbO  = ni * 128;       // O-phase n base (128 cols per warp)

    // q tile: [t][r]
    for (int i = tid; i < BM*RR; i += 256) {
        int r = i >> 6, tq = i & 63;
        q_s[tq*QP + r] = g_Q[(b*RR + r)*TT + t0 + tq];
    }
    if (tid < BM) { m_s[tid] = -1e30f; l_s[tid] = 0.f; }

    float acc[16][4];
    #pragma unroll
    for (int nf = 0; nf < 16; nf++)
        #pragma unroll
        for (int j = 0; j < 4; j++) acc[nf][j] = 0.f;

    const int row  = tid >> 2, part = tid & 3;  // softmax map

    for (int s0 = 0; s0 < TT; s0 += BN) {
        __syncthreads();
        // K tile [32][64]
        for (int i = tid; i < RR*(BN/4); i += 256) {
            int r = i >> 4, sq = i & 15;
            float4 kv = *reinterpret_cast<const float4*>(&g_K[(b*RR + r)*TT + s0 + sq*4]);
            *reinterpret_cast<float4*>(&k_s[r*KP + sq*4]) = kv;
        }
        // V tile [256][64]
        for (int i = tid; i < CC*(BN/4); i += 256) {
            int c = i >> 4, sq = i & 15;
            float4 vv = *reinterpret_cast<const float4*>(&g_V[(b*CC + c)*TT + s0 + sq*4]);
            *reinterpret_cast<float4*>(&v_s[c*VP + sq*4]) = vv;
        }
        __syncthreads();

        // ---- S = Q @ K : warp m16 x n32, K = 32 (4 k-steps) ----
        {
            float sacc[4][4];
            #pragma unroll
            for (int nf = 0; nf < 4; nf++)
                #pragma unroll
                for (int j = 0; j < 4; j++) sacc[nf][j] = 0.f;
            #pragma unroll
            for (int ks = 0; ks < 4; ks++) {
                int k0 = ks*8;
                uint32_t a0 = fbits(q_s[mrow*QP     + k0 + lr]);
                uint32_t a1 = fbits(q_s[(mrow+8)*QP + k0 + lr]);
                uint32_t a2 = fbits(q_s[mrow*QP     + k0 + lr + 4]);
                uint32_t a3 = fbits(q_s[(mrow+8)*QP + k0 + lr + 4]);
                #pragma unroll
                for (int nf = 0; nf < 4; nf++) {
                    int n0 = ni*32 + nf*8;
                    uint32_t b0 = fbits(k_s[(k0+lr  )*KP + n0 + lq]);
                    uint32_t b1 = fbits(k_s[(k0+lr+4)*KP + n0 + lq]);
                    mma8(sacc[nf], a0, a1, a2, a3, b0, b1);
                }
            }
            #pragma unroll
            for (int nf = 0; nf < 4; nf++) {
                int col = ni*32 + nf*8 + lr*2;
                s_s[mrow*SP     + col    ] = sacc[nf][0];
                s_s[mrow*SP     + col + 1] = sacc[nf][1];
                s_s[(mrow+8)*SP + col    ] = sacc[nf][2];
                s_s[(mrow+8)*SP + col + 1] = sacc[nf][3];
            }
        }
        __syncthreads();

        // ---- online softmax: 4 threads per row ----
        {
            float* sr = &s_s[row*SP + part*16];
            float lmax = -1e30f;
            #pragma unroll
            for (int i = 0; i < 16; i++) lmax = fmaxf(lmax, sr[i]);
            lmax = fmaxf(lmax, __shfl_xor_sync(0xffffffffu, lmax, 1));
            lmax = fmaxf(lmax, __shfl_xor_sync(0xffffffffu, lmax, 2));
            float m_old = m_s[row];
            float m_new = fmaxf(m_old, lmax);
            float lsum = 0.f;
            #pragma unroll
            for (int i = 0; i < 16; i++) {
                float p = __expf(sr[i] - m_new);
                sr[i] = p; lsum += p;
            }
            lsum += __shfl_xor_sync(0xffffffffu, lsum, 1);
            lsum += __shfl_xor_sync(0xffffffffu, lsum, 2);
            if (part == 0) {
                float alpha = __expf(m_old - m_new);
                a_s[row] = alpha;
                l_s[row] = l_s[row]*alpha + lsum;
                m_s[row] = m_new;
            }
        }
        __syncthreads();

        // ---- O = alpha*O + P @ V : warp m16 x n128, K = 64 (8 k-steps) ----
        {
            float al0 = a_s[mrow], al1 = a_s[mrow+8];
            #pragma unroll
            for (int nf = 0; nf < 16; nf++) {
                acc[nf][0] *= al0; acc[nf][1] *= al0;
                acc[nf][2] *= al1; acc[nf][3] *= al1;
            }
            #pragma unroll
            for (int ks = 0; ks < 8; ks++) {
                int k0 = ks*8;
                uint32_t a0 = fbits(s_s[mrow*SP     + k0 + lr]);
                uint32_t a1 = fbits(s_s[(mrow+8)*SP + k0 + lr]);
                uint32_t a2 = fbits(s_s[mrow*SP     + k0 + lr + 4]);
                uint32_t a3 = fbits(s_s[(mrow+8)*SP + k0 + lr + 4]);
                #pragma unroll
                for (int nf = 0; nf < 16; nf++) {
                    int n0 = nbO + nf*8;
                    uint32_t b0 = fbits(v_s[(n0+lq)*VP + k0 + lr]);
                    uint32_t b1 = fbits(v_s[(n0+lq)*VP + k0 + lr + 4]);
                    mma8(acc[nf], a0, a1, a2, a3, b0, b1);
                }
            }
        }
    }
    __syncthreads();

    // ---- epilogue: y[b][c][t] = x + gamma * O/l ----
    const float gm  = gamma[0];
    const float inv0 = 1.0f / l_s[mrow];
    const float inv1 = 1.0f / l_s[mrow+8];
    #pragma unroll
    for (int nf = 0; nf < 16; nf++) {
        int c = nbO + nf*8 + lr*2;
        size_t i0 = ((size_t)(b*CC + c))*TT + t0 + mrow;   // (c, row)
        out[i0       ] = x[i0       ] + gm*acc[nf][0]*inv0;
        out[i0 + TT  ] = x[i0 + TT  ] + gm*acc[nf][1]*inv0;  // c+1, row
        out[i0 + 8   ] = x[i0 + 8   ] + gm*acc[nf][2]*inv1;  // c,   row+8
        out[i0+TT+ 8 ] = x[i0+TT+ 8 ] + gm*acc[nf][3]*inv1;  // c+1, row+8
    }
}

// ---------------------------------------------------------------------------
extern "C" void kernel_launch(void* const* d_in, const int* in_sizes, int n_in,
                              void* d_out, int out_size) {
    const float* x     = (const float*)d_in[0];
    const float* Wq    = (const float*)d_in[1];
    const float* bq    = (const float*)d_in[2];
    const float* Wk    = (const float*)d_in[3];
    const float* bk    = (const float*)d_in[4];
    const float* Wv    = (const float*)d_in[5];
    const float* bv    = (const float*)d_in[6];
    const float* gamma = (const float*)d_in[7];
    float* out = (float*)d_out;

    (void)in_sizes; (void)n_in; (void)out_size;

    cudaFuncSetAttribute(attn_kernel, cudaFuncAttributeMaxDynamicSharedMemorySize,
                         ATTN_SMEM_FLOATS * (int)sizeof(float));

    dim3 g1(TT/128, 5, BB);
    proj_kernel<<<g1, 256>>>(x, Wq, bq, Wk, bk, Wv, bv);

    dim3 g2(TT/BM, BB);
    attn_kernel<<<g2, 256, ATTN_SMEM_FLOATS * sizeof(float)>>>(x, gamma, out);
}

// round 4
// speedup vs baseline: 2.2156x; 1.0123x over previous
#include <cuda_runtime.h>
#include <cstdint>

#define BB 8
#define CC 256
#define TT 2048
#define RR 32

// Scratch (allocation-free rule: __device__ globals)
__device__ float g_Q[BB*RR*TT];   // [b][r][t]
__device__ float g_K[BB*RR*TT];   // [b][r][t]
__device__ float g_V[BB*CC*TT];   // [b][c][t]

// ---------------------------------------------------------------------------
// Kernel 1: fused projections (fp32 SIMT, unchanged this round).
// ---------------------------------------------------------------------------
__global__ __launch_bounds__(256) void proj_kernel(
    const float* __restrict__ x,
    const float* __restrict__ Wq, const float* __restrict__ bq,
    const float* __restrict__ Wk, const float* __restrict__ bk,
    const float* __restrict__ Wv, const float* __restrict__ bv)
{
    const int b   = blockIdx.z;
    const int g   = blockIdx.y;          // 0: q(32)+k(32) rows, 1..4: v rows
    const int t0  = blockIdx.x * 128;
    const int tid = threadIdx.x;

    __shared__ float w_s[64*33];
    __shared__ float x_s[32*132];

    float acc[4][8];
    #pragma unroll
    for (int i = 0; i < 4; i++)
        #pragma unroll
        for (int j = 0; j < 8; j++) acc[i][j] = 0.f;

    const int ty = tid >> 4, tx = tid & 15;

    for (int cc = 0; cc < CC; cc += 32) {
        for (int i = tid; i < 64*32; i += 256) {
            int r = i >> 5, c = i & 31;
            float wv;
            if (g == 0) {
                wv = (r < 32) ? Wq[r*CC + cc + c] : Wk[(r-32)*CC + cc + c];
            } else {
                wv = Wv[((g-1)*64 + r)*CC + cc + c];
            }
            w_s[r*33 + c] = wv;
        }
        for (int i = tid; i < 32*32; i += 256) {
            int c = i >> 5, tq = i & 31;
            float4 xv = *reinterpret_cast<const float4*>(&x[(b*CC + cc + c)*TT + t0 + tq*4]);
            *reinterpret_cast<float4*>(&x_s[c*132 + tq*4]) = xv;
        }
        __syncthreads();
        #pragma unroll
        for (int c = 0; c < 32; c++) {
            float wr[4], xr[8];
            #pragma unroll
            for (int i = 0; i < 4; i++) wr[i] = w_s[(ty*4+i)*33 + c];
            #pragma unroll
            for (int j = 0; j < 8; j++) xr[j] = x_s[c*132 + tx*8 + j];
            #pragma unroll
            for (int i = 0; i < 4; i++)
                #pragma unroll
                for (int j = 0; j < 8; j++)
                    acc[i][j] += wr[i] * xr[j];
        }
        __syncthreads();
    }

    #pragma unroll
    for (int i = 0; i < 4; i++) {
        int r = ty*4 + i;
        float bias; float* dst;
        if (g == 0) {
            if (r < 32) { bias = bq[r];    dst = &g_Q[(b*RR + r   )*TT]; }
            else        { bias = bk[r-32]; dst = &g_K[(b*RR + r-32)*TT]; }
        } else {
            int vr = (g-1)*64 + r;
            bias = bv[vr]; dst = &g_V[(b*CC + vr)*TT];
        }
        #pragma unroll
        for (int jj = 0; jj < 2; jj++) {
            float4 o;
            o.x = acc[i][jj*4+0] + bias; o.y = acc[i][jj*4+1] + bias;
            o.z = acc[i][jj*4+2] + bias; o.w = acc[i][jj*4+3] + bias;
            *reinterpret_cast<float4*>(&dst[t0 + tx*8 + jj*4]) = o;
        }
    }
}

// ---------------------------------------------------------------------------
// Kernel 2: flash attention with tf32 mma.sync (m16n8k8).
// Grid: (T/64, B).  256 threads = 8 warps, 2 CTAs/SM.
// Warp S-tile: m16 x n32.  Warp O-tile: m16 x n128 (64 fp32 acc regs).
// ---------------------------------------------------------------------------
#define BM 64
#define BN 64
#define QP 36
#define KP 72
#define VP 68
#define SP 68
#define SM_K (BM*QP)
#define SM_V (SM_K + RR*KP)
#define SM_S (SM_V + CC*VP)
#define SM_M (SM_S + BM*SP)
#define ATTN_SMEM_FLOATS (SM_M + 3*BM)

__device__ __forceinline__ void mma8(float* d,
    uint32_t a0, uint32_t a1, uint32_t a2, uint32_t a3,
    uint32_t b0, uint32_t b1)
{
    asm volatile(
        "mma.sync.aligned.m16n8k8.row.col.f32.tf32.tf32.f32 "
        "{%0,%1,%2,%3}, {%4,%5,%6,%7}, {%8,%9}, {%0,%1,%2,%3};"
        : "+f"(d[0]), "+f"(d[1]), "+f"(d[2]), "+f"(d[3])
        : "r"(a0), "r"(a1), "r"(a2), "r"(a3), "r"(b0), "r"(b1));
}

__device__ __forceinline__ uint32_t fbits(float f) { return __float_as_uint(f); }

__global__ __launch_bounds__(256, 2) void attn_kernel(
    const float* __restrict__ x, const float* __restrict__ gamma,
    float* __restrict__ out)
{
    extern __shared__ float sm[];
    float* q_s = sm;                 // [64][36]  q_s[t][r]
    float* k_s = sm + SM_K;          // [32][72]  k_s[r][s]
    float* v_s = sm + SM_V;          // [256][68] v_s[c][s]
    float* s_s = sm + SM_S;          // [64][68]  scores / probs
    float* m_s = sm + SM_M;          // [64]
    float* l_s = m_s + BM;           // [64]
    float* a_s = l_s + BM;           // [64]

    const int b    = blockIdx.y;
    const int t0   = blockIdx.x * BM;
    const int tid  = threadIdx.x;
    const int wid  = tid >> 5;
    const int lane = tid & 31;
    const int lq   = lane >> 2;      // 0..7
    const int lr   = lane & 3;       // 0..3
    const int mi   = wid >> 1;       // 0..3 -> 16-row chunk
    const int ni   = wid & 1;        // 0..1
    const int mrow = mi*16 + lq;     // this thread's first m row (and mrow+8)
    const int nbO  = ni * 128;       // O-phase n base (128 cols per warp)

    // q tile: [t][r]
    for (int i = tid; i < BM*RR; i += 256) {
        int r = i >> 6, tq = i & 63;
        q_s[tq*QP + r] = g_Q[(b*RR + r)*TT + t0 + tq];
    }
    if (tid < BM) { m_s[tid] = -1e30f; l_s[tid] = 0.f; }

    float acc[16][4];
    #pragma unroll
    for (int nf = 0; nf < 16; nf++)
        #pragma unroll
        for (int j = 0; j < 4; j++) acc[nf][j] = 0.f;

    const int row  = tid >> 2, part = tid & 3;  // softmax map

    for (int s0 = 0; s0 < TT; s0 += BN) {
        __syncthreads();
        // K tile [32][64]
        for (int i = tid; i < RR*(BN/4); i += 256) {
            int r = i >> 4, sq = i & 15;
            float4 kv = *reinterpret_cast<const float4*>(&g_K[(b*RR + r)*TT + s0 + sq*4]);
            *reinterpret_cast<float4*>(&k_s[r*KP + sq*4]) = kv;
        }
        // V tile [256][64]
        for (int i = tid; i < CC*(BN/4); i += 256) {
            int c = i >> 4, sq = i & 15;
            float4 vv = *reinterpret_cast<const float4*>(&g_V[(b*CC + c)*TT + s0 + sq*4]);
            *reinterpret_cast<float4*>(&v_s[c*VP + sq*4]) = vv;
        }
        __syncthreads();

        // ---- S = Q @ K : warp m16 x n32, K = 32 (4 k-steps) ----
        {
            float sacc[4][4];
            #pragma unroll
            for (int nf = 0; nf < 4; nf++)
                #pragma unroll
                for (int j = 0; j < 4; j++) sacc[nf][j] = 0.f;
            #pragma unroll
            for (int ks = 0; ks < 4; ks++) {
                int k0 = ks*8;
                uint32_t a0 = fbits(q_s[mrow*QP     + k0 + lr]);
                uint32_t a1 = fbits(q_s[(mrow+8)*QP + k0 + lr]);
                uint32_t a2 = fbits(q_s[mrow*QP     + k0 + lr + 4]);
                uint32_t a3 = fbits(q_s[(mrow+8)*QP + k0 + lr + 4]);
                #pragma unroll
                for (int nf = 0; nf < 4; nf++) {
                    int n0 = ni*32 + nf*8;
                    uint32_t b0 = fbits(k_s[(k0+lr  )*KP + n0 + lq]);
                    uint32_t b1 = fbits(k_s[(k0+lr+4)*KP + n0 + lq]);
                    mma8(sacc[nf], a0, a1, a2, a3, b0, b1);
                }
            }
            #pragma unroll
            for (int nf = 0; nf < 4; nf++) {
                int col = ni*32 + nf*8 + lr*2;
                s_s[mrow*SP     + col    ] = sacc[nf][0];
                s_s[mrow*SP     + col + 1] = sacc[nf][1];
                s_s[(mrow+8)*SP + col    ] = sacc[nf][2];
                s_s[(mrow+8)*SP + col + 1] = sacc[nf][3];
            }
        }
        __syncthreads();

        // ---- online softmax: 4 threads per row ----
        {
            float* sr = &s_s[row*SP + part*16];
            float lmax = -1e30f;
            #pragma unroll
            for (int i = 0; i < 16; i++) lmax = fmaxf(lmax, sr[i]);
            lmax = fmaxf(lmax, __shfl_xor_sync(0xffffffffu, lmax, 1));
            lmax = fmaxf(lmax, __shfl_xor_sync(0xffffffffu, lmax, 2));
            float m_old = m_s[row];
            float m_new = fmaxf(m_old, lmax);
            float lsum = 0.f;
            #pragma unroll
            for (int i = 0; i < 16; i++) {
                float p = __expf(sr[i] - m_new);
                sr[i] = p; lsum += p;
            }
            lsum += __shfl_xor_sync(0xffffffffu, lsum, 1);
            lsum += __shfl_xor_sync(0xffffffffu, lsum, 2);
            if (part == 0) {
                float alpha = __expf(m_old - m_new);
                a_s[row] = alpha;
                l_s[row] = l_s[row]*alpha + lsum;
                m_s[row] = m_new;
            }
        }
        __syncthreads();

        // ---- O = alpha*O + P @ V : warp m16 x n128, K = 64 (8 k-steps) ----
        {
            float al0 = a_s[mrow], al1 = a_s[mrow+8];
            #pragma unroll
            for (int nf = 0; nf < 16; nf++) {
                acc[nf][0] *= al0; acc[nf][1] *= al0;
                acc[nf][2] *= al1; acc[nf][3] *= al1;
            }
            #pragma unroll
            for (int ks = 0; ks < 8; ks++) {
                int k0 = ks*8;
                uint32_t a0 = fbits(s_s[mrow*SP     + k0 + lr]);
                uint32_t a1 = fbits(s_s[(mrow+8)*SP + k0 + lr]);
                uint32_t a2 = fbits(s_s[mrow*SP     + k0 + lr + 4]);
                uint32_t a3 = fbits(s_s[(mrow+8)*SP + k0 + lr + 4]);
                #pragma unroll
                for (int nf = 0; nf < 16; nf++) {
                    int n0 = nbO + nf*8;
                    uint32_t b0 = fbits(v_s[(n0+lq)*VP + k0 + lr]);
                    uint32_t b1 = fbits(v_s[(n0+lq)*VP + k0 + lr + 4]);
                    mma8(acc[nf], a0, a1, a2, a3, b0, b1);
                }
            }
        }
    }
    __syncthreads();

    // ---- epilogue: y[b][c][t] = x + gamma * O/l ----
    const float gm  = gamma[0];
    const float inv0 = 1.0f / l_s[mrow];
    const float inv1 = 1.0f / l_s[mrow+8];
    #pragma unroll
    for (int nf = 0; nf < 16; nf++) {
        int c = nbO + nf*8 + lr*2;
        size_t i0 = ((size_t)(b*CC + c))*TT + t0 + mrow;   // (c, row)
        out[i0       ] = x[i0       ] + gm*acc[nf][0]*inv0;
        out[i0 + TT  ] = x[i0 + TT  ] + gm*acc[nf][1]*inv0;  // c+1, row
        out[i0 + 8   ] = x[i0 + 8   ] + gm*acc[nf][2]*inv1;  // c,   row+8
        out[i0+TT+ 8 ] = x[i0+TT+ 8 ] + gm*acc[nf][3]*inv1;  // c+1, row+8
    }
}

// ---------------------------------------------------------------------------
extern "C" void kernel_launch(void* const* d_in, const int* in_sizes, int n_in,
                              void* d_out, int out_size) {
    const float* x     = (const float*)d_in[0];
    const float* Wq    = (const float*)d_in[1];
    const float* bq    = (const float*)d_in[2];
    const float* Wk    = (const float*)d_in[3];
    const float* bk    = (const float*)d_in[4];
    const float* Wv    = (const float*)d_in[5];
    const float* bv    = (const float*)d_in[6];
    const float* gamma = (const float*)d_in[7];
    float* out = (float*)d_out;

    (void)in_sizes; (void)n_in; (void)out_size;

    cudaFuncSetAttribute(attn_kernel, cudaFuncAttributeMaxDynamicSharedMemorySize,
                         ATTN_SMEM_FLOATS * (int)sizeof(float));

    dim3 g1(TT/128, 5, BB);
    proj_kernel<<<g1, 256>>>(x, Wq, bq, Wk, bk, Wv, bv);

    dim3 g2(TT/BM, BB);
    attn_kernel<<<g2, 256, ATTN_SMEM_FLOATS * sizeof(float)>>>(x, gamma, out);
}

// round 5
// speedup vs baseline: 3.3441x; 1.5093x over previous
#include <cuda_runtime.h>
#include <cuda_bf16.h>
#include <cstdint>

#define BB 8
#define CC 256
#define TT 2048
#define RR 32

// bf16 scratch in attention-friendly layouts
__device__ __nv_bfloat16 g_Qb[BB*TT*RR];   // [b][t][r]
__device__ __nv_bfloat16 g_Kb[BB*TT*RR];   // [b][t][r]   (t is the s dim)
__device__ __nv_bfloat16 g_Vb[BB*CC*TT];   // [b][c][t]

// ---------------------------------------------------------------------------
// PTX helpers
// ---------------------------------------------------------------------------
__device__ __forceinline__ uint32_t smaddr(const void* p) {
    return (uint32_t)__cvta_generic_to_shared(p);
}
__device__ __forceinline__ void cp16(void* dst, const void* src) {
    asm volatile("cp.async.cg.shared.global [%0], [%1], 16;"
                 :: "r"(smaddr(dst)), "l"(src) : "memory");
}
__device__ __forceinline__ void cpcommit() {
    asm volatile("cp.async.commit_group;" ::: "memory");
}
__device__ __forceinline__ void cpwait0() {
    asm volatile("cp.async.wait_group 0;" ::: "memory");
}
__device__ __forceinline__ void ldsm4(uint32_t* r, const void* p) {
    asm volatile("ldmatrix.sync.aligned.m8n8.x4.shared.b16 {%0,%1,%2,%3}, [%4];"
        : "=r"(r[0]), "=r"(r[1]), "=r"(r[2]), "=r"(r[3])
        : "r"(smaddr(p)));
}
__device__ __forceinline__ void mmabf(float* d, const uint32_t* a,
                                      uint32_t b0, uint32_t b1) {
    asm volatile(
        "mma.sync.aligned.m16n8k16.row.col.f32.bf16.bf16.f32 "
        "{%0,%1,%2,%3},{%4,%5,%6,%7},{%8,%9},{%0,%1,%2,%3};"
        : "+f"(d[0]), "+f"(d[1]), "+f"(d[2]), "+f"(d[3])
        : "r"(a[0]), "r"(a[1]), "r"(a[2]), "r"(a[3]), "r"(b0), "r"(b1));
}

// ---------------------------------------------------------------------------
// Kernel 1: projections (fp32 SIMT), emitting bf16 in mma-ready layouts.
// Grid: (T/128, 5, B).  Groups: 0 = Q(32)+K(32) rows, 1..4 = V 64-row slabs.
// ---------------------------------------------------------------------------
__global__ __launch_bounds__(256) void proj_kernel(
    const float* __restrict__ x,
    const float* __restrict__ Wq, const float* __restrict__ bq,
    const float* __restrict__ Wk, const float* __restrict__ bk,
    const float* __restrict__ Wv, const float* __restrict__ bv)
{
    const int b   = blockIdx.z;
    const int g   = blockIdx.y;
    const int t0  = blockIdx.x * 128;
    const int tid = threadIdx.x;

    __shared__ float w_s[64*33];
    __shared__ float x_s[32*132];

    float acc[4][8];
    #pragma unroll
    for (int i = 0; i < 4; i++)
        #pragma unroll
        for (int j = 0; j < 8; j++) acc[i][j] = 0.f;

    const int ty = tid >> 4, tx = tid & 15;

    for (int cc = 0; cc < CC; cc += 32) {
        for (int i = tid; i < 64*32; i += 256) {
            int r = i >> 5, c = i & 31;
            float wv;
            if (g == 0) {
                wv = (r < 32) ? Wq[r*CC + cc + c] : Wk[(r-32)*CC + cc + c];
            } else {
                wv = Wv[((g-1)*64 + r)*CC + cc + c];
            }
            w_s[r*33 + c] = wv;
        }
        for (int i = tid; i < 32*32; i += 256) {
            int c = i >> 5, tq = i & 31;
            float4 xv = *reinterpret_cast<const float4*>(&x[(b*CC + cc + c)*TT + t0 + tq*4]);
            *reinterpret_cast<float4*>(&x_s[c*132 + tq*4]) = xv;
        }
        __syncthreads();
        #pragma unroll
        for (int c = 0; c < 32; c++) {
            float wr[4], xr[8];
            #pragma unroll
            for (int i = 0; i < 4; i++) wr[i] = w_s[(ty*4+i)*33 + c];
            #pragma unroll
            for (int j = 0; j < 8; j++) xr[j] = x_s[c*132 + tx*8 + j];
            #pragma unroll
            for (int i = 0; i < 4; i++)
                #pragma unroll
                for (int j = 0; j < 8; j++)
                    acc[i][j] += wr[i] * xr[j];
        }
        __syncthreads();
    }

    #pragma unroll
    for (int i = 0; i < 4; i++) {
        int r = ty*4 + i;
        if (g == 0) {
            // Q or K rows -> bf16 [b][t][r] (scalar stores; tiny volume)
            float bias = (r < 32) ? bq[r] : bk[r-32];
            __nv_bfloat16* base = (r < 32) ? g_Qb : g_Kb;
            int rr = (r < 32) ? r : r - 32;
            #pragma unroll
            for (int j = 0; j < 8; j++) {
                int t = t0 + tx*8 + j;
                base[((size_t)b*TT + t)*RR + rr] = __float2bfloat16(acc[i][j] + bias);
            }
        } else {
            // V rows -> bf16 [b][c][t], 8B packed stores
            int vr = (g-1)*64 + r;
            float bias = bv[vr];
            #pragma unroll
            for (int jj = 0; jj < 2; jj++) {
                __nv_bfloat162 h0 = __floats2bfloat162_rn(acc[i][jj*4+0] + bias,
                                                          acc[i][jj*4+1] + bias);
                __nv_bfloat162 h1 = __floats2bfloat162_rn(acc[i][jj*4+2] + bias,
                                                          acc[i][jj*4+3] + bias);
                uint2 pk;
                pk.x = *reinterpret_cast<uint32_t*>(&h0);
                pk.y = *reinterpret_cast<uint32_t*>(&h1);
                *reinterpret_cast<uint2*>(
                    &g_Vb[((size_t)b*CC + vr)*TT + t0 + tx*8 + jj*4]) = pk;
            }
        }
    }
}

// ---------------------------------------------------------------------------
// Kernel 2: flash attention, bf16 mma m16n8k16 + ldmatrix + cp.async pipeline.
// Grid: (T/64, B).  8 warps.  Warp (mi=w>>1, ni=w&1):
//   S phase : m16 (rows mi*16..) x n32 (cols ni*32..), Q frags hoisted in regs
//   softmax : in registers (mma layout), cross-warp row stats via 1KB smem
//   PV phase: P via bf16 smem + ldmatrix, O warp tile m16 x n128 (cols ni*128..)
// ---------------------------------------------------------------------------
#define QPH 40
#define KPH 40
#define VPH 72
#define PPH 72
#define KBUF (64*KPH)
#define VBUF (CC*VPH)
#define SM_HALVES (64*QPH + 2*KBUF + 2*VBUF + 64*PPH)
#define SM_BYTES  (SM_HALVES*2 + 2*128*4)

__global__ __launch_bounds__(256, 2) void attn_kernel(
    const float* __restrict__ x, const float* __restrict__ gamma,
    float* __restrict__ out)
{
    extern __shared__ __align__(16) char smraw[];
    __nv_bfloat16* q_s = (__nv_bfloat16*)smraw;          // [64][40]
    __nv_bfloat16* k_s = q_s + 64*QPH;                   // [2][64][40]
    __nv_bfloat16* v_s = k_s + 2*KBUF;                   // [2][256][72]
    __nv_bfloat16* p_s = v_s + 2*VBUF;                   // [64][72]
    float* ex_max = (float*)(p_s + 64*PPH);              // [8][16]
    float* ex_sum = ex_max + 128;                        // [8][16]

    const int b    = blockIdx.y;
    const int t0   = blockIdx.x * 64;
    const int tid  = threadIdx.x;
    const int wid  = tid >> 5;
    const int lane = tid & 31;
    const int lq   = lane >> 2, lr = lane & 3;
    const int mi   = wid >> 1,  ni = wid & 1;
    const int l8   = (lane & 7) + ((lane & 8) ? 8 : 0);  // ldmatrix row-in-16
    const int lc   = (lane >> 4) * 8;                    // ldmatrix col half

    // ---- prefetch tile 0 ----
    {
        #pragma unroll
        for (int j = 0; j < 9; j++) {
            int slot = tid + j*256;
            if (slot < 256) {
                int row = slot >> 2, ch = slot & 3;
                cp16(&k_s[row*KPH + ch*8],
                     &g_Kb[((size_t)b*TT + row)*RR + ch*8]);
            } else {
                int vsl = slot - 256;
                int row = vsl >> 3, ch = vsl & 7;
                cp16(&v_s[row*VPH + ch*8],
                     &g_Vb[((size_t)b*CC + row)*TT + ch*8]);
            }
        }
        cpcommit();
    }

    // ---- stage Q and hoist A fragments (once per CTA) ----
    {
        int row = tid >> 2, ch = tid & 3;
        uint4 qv = *reinterpret_cast<const uint4*>(
            &g_Qb[((size_t)b*TT + t0 + row)*RR + ch*8]);
        *reinterpret_cast<uint4*>(&q_s[row*QPH + ch*8]) = qv;
    }
    __syncthreads();
    uint32_t aq[8];
    ldsm4(aq,     &q_s[(mi*16 + l8)*QPH + lc]);
    ldsm4(aq + 4, &q_s[(mi*16 + l8)*QPH + 16 + lc]);

    float acc[16][4];
    #pragma unroll
    for (int nf = 0; nf < 16; nf++)
        #pragma unroll
        for (int j = 0; j < 4; j++) acc[nf][j] = 0.f;
    float m_prev[2] = {-1e30f, -1e30f};
    float l_run[2]  = {0.f, 0.f};

    for (int it = 0; it < TT/64; it++) {
        const int buf = it & 1;
        cpwait0();
        __syncthreads();                       // buffers ready; prev p_s consumed

        if (it + 1 < TT/64) {                  // prefetch next tile
            const int s0 = (it+1)*64;
            __nv_bfloat16* kd = k_s + (buf^1)*KBUF;
            __nv_bfloat16* vd = v_s + (buf^1)*VBUF;
            #pragma unroll
            for (int j = 0; j < 9; j++) {
                int slot = tid + j*256;
                if (slot < 256) {
                    int row = slot >> 2, ch = slot & 3;
                    cp16(&kd[row*KPH + ch*8],
                         &g_Kb[((size_t)b*TT + s0 + row)*RR + ch*8]);
                } else {
                    int vsl = slot - 256;
                    int row = vsl >> 3, ch = vsl & 7;
                    cp16(&vd[row*VPH + ch*8],
                         &g_Vb[((size_t)b*CC + row)*TT + s0 + ch*8]);
                }
            }
            cpcommit();
        }

        // ---- S = Q @ K^T : warp m16 x n32 ----
        const __nv_bfloat16* kb = k_s + buf*KBUF;
        float sacc[4][4];
        #pragma unroll
        for (int g = 0; g < 4; g++)
            #pragma unroll
            for (int j = 0; j < 4; j++) sacc[g][j] = 0.f;
        #pragma unroll
        for (int ks = 0; ks < 2; ks++) {
            #pragma unroll
            for (int n2 = 0; n2 < 2; n2++) {
                uint32_t kb4[4];
                ldsm4(kb4, &kb[(ni*32 + n2*16 + l8)*KPH + ks*16 + lc]);
                mmabf(sacc[n2*2+0], aq + ks*4, kb4[0], kb4[2]);
                mmabf(sacc[n2*2+1], aq + ks*4, kb4[1], kb4[3]);
            }
        }

        // ---- online softmax (registers + cross-warp exchange) ----
        float mx0 = fmaxf(fmaxf(sacc[0][0], sacc[0][1]), fmaxf(sacc[1][0], sacc[1][1]));
        mx0 = fmaxf(mx0, fmaxf(fmaxf(sacc[2][0], sacc[2][1]), fmaxf(sacc[3][0], sacc[3][1])));
        float mx1 = fmaxf(fmaxf(sacc[0][2], sacc[0][3]), fmaxf(sacc[1][2], sacc[1][3]));
        mx1 = fmaxf(mx1, fmaxf(fmaxf(sacc[2][2], sacc[2][3]), fmaxf(sacc[3][2], sacc[3][3])));
        mx0 = fmaxf(mx0, __shfl_xor_sync(0xffffffffu, mx0, 1));
        mx0 = fmaxf(mx0, __shfl_xor_sync(0xffffffffu, mx0, 2));
        mx1 = fmaxf(mx1, __shfl_xor_sync(0xffffffffu, mx1, 1));
        mx1 = fmaxf(mx1, __shfl_xor_sync(0xffffffffu, mx1, 2));
        if (lr == 0) { ex_max[wid*16 + lq] = mx0; ex_max[wid*16 + 8 + lq] = mx1; }
        __syncthreads();
        mx0 = fmaxf(mx0, ex_max[(wid^1)*16 + lq]);
        mx1 = fmaxf(mx1, ex_max[(wid^1)*16 + 8 + lq]);
        float mn0 = fmaxf(m_prev[0], mx0), mn1 = fmaxf(m_prev[1], mx1);
        float al0 = __expf(m_prev[0] - mn0), al1 = __expf(m_prev[1] - mn1);
        m_prev[0] = mn0; m_prev[1] = mn1;

        float sum0 = 0.f, sum1 = 0.f;
        #pragma unroll
        for (int g = 0; g < 4; g++) {
            sacc[g][0] = __expf(sacc[g][0] - mn0);
            sacc[g][1] = __expf(sacc[g][1] - mn0);
            sacc[g][2] = __expf(sacc[g][2] - mn1);
            sacc[g][3] = __expf(sacc[g][3] - mn1);
            sum0 += sacc[g][0] + sacc[g][1];
            sum1 += sacc[g][2] + sacc[g][3];
        }
        sum0 += __shfl_xor_sync(0xffffffffu, sum0, 1);
        sum0 += __shfl_xor_sync(0xffffffffu, sum0, 2);
        sum1 += __shfl_xor_sync(0xffffffffu, sum1, 1);
        sum1 += __shfl_xor_sync(0xffffffffu, sum1, 2);
        if (lr == 0) { ex_sum[wid*16 + lq] = sum0; ex_sum[wid*16 + 8 + lq] = sum1; }

        // P -> smem (bf16x2, conflict-free)
        #pragma unroll
        for (int g = 0; g < 4; g++) {
            int cb = ni*32 + g*8 + 2*lr;
            __nv_bfloat162 plo = __floats2bfloat162_rn(sacc[g][0], sacc[g][1]);
            __nv_bfloat162 phi = __floats2bfloat162_rn(sacc[g][2], sacc[g][3]);
            *reinterpret_cast<__nv_bfloat162*>(&p_s[(mi*16 + lq)*PPH + cb])     = plo;
            *reinterpret_cast<__nv_bfloat162*>(&p_s[(mi*16 + 8 + lq)*PPH + cb]) = phi;
        }
        // rescale accumulators
        #pragma unroll
        for (int nf = 0; nf < 16; nf++) {
            acc[nf][0] *= al0; acc[nf][1] *= al0;
            acc[nf][2] *= al1; acc[nf][3] *= al1;
        }
        __syncthreads();
        l_run[0] = l_run[0]*al0 + sum0 + ex_sum[(wid^1)*16 + lq];
        l_run[1] = l_run[1]*al1 + sum1 + ex_sum[(wid^1)*16 + 8 + lq];

        // ---- O += P @ V : warp m16 x n128, full k64 ----
        const __nv_bfloat16* vb = v_s + buf*VBUF;
        #pragma unroll
        for (int ks = 0; ks < 4; ks++) {
            uint32_t pa[4];
            ldsm4(pa, &p_s[(mi*16 + l8)*PPH + ks*16 + lc]);
            #pragma unroll
            for (int cg = 0; cg < 8; cg++) {
                uint32_t vb4[4];
                ldsm4(vb4, &vb[(ni*128 + cg*16 + l8)*VPH + ks*16 + lc]);
                mmabf(acc[cg*2+0], pa, vb4[0], vb4[2]);
                mmabf(acc[cg*2+1], pa, vb4[1], vb4[3]);
            }
        }
    }

    // ---- epilogue: y[b][c][t] = x + gamma * O/l ----
    const float gm   = gamma[0];
    const float inv0 = 1.0f / l_run[0];
    const float inv1 = 1.0f / l_run[1];
    const int   trow = t0 + mi*16 + lq;
    #pragma unroll
    for (int nf = 0; nf < 16; nf++) {
        int c = ni*128 + (nf >> 1)*16 + (nf & 1)*8 + 2*lr;
        size_t i0 = ((size_t)(b*CC + c))*TT + trow;
        out[i0      ] = x[i0      ] + gm*acc[nf][0]*inv0;
        out[i0 + TT ] = x[i0 + TT ] + gm*acc[nf][1]*inv0;
        out[i0 + 8  ] = x[i0 + 8  ] + gm*acc[nf][2]*inv1;
        out[i0+TT+8 ] = x[i0+TT+8 ] + gm*acc[nf][3]*inv1;
    }
}

// ---------------------------------------------------------------------------
extern "C" void kernel_launch(void* const* d_in, const int* in_sizes, int n_in,
                              void* d_out, int out_size) {
    const float* x     = (const float*)d_in[0];
    const float* Wq    = (const float*)d_in[1];
    const float* bq    = (const float*)d_in[2];
    const float* Wk    = (const float*)d_in[3];
    const float* bk    = (const float*)d_in[4];
    const float* Wv    = (const float*)d_in[5];
    const float* bv    = (const float*)d_in[6];
    const float* gamma = (const float*)d_in[7];
    float* out = (float*)d_out;

    (void)in_sizes; (void)n_in; (void)out_size;

    cudaFuncSetAttribute(attn_kernel, cudaFuncAttributeMaxDynamicSharedMemorySize,
                         SM_BYTES);

    dim3 g1(TT/128, 5, BB);
    proj_kernel<<<g1, 256>>>(x, Wq, bq, Wk, bk, Wv, bv);

    dim3 g2(TT/64, BB);
    attn_kernel<<<g2, 256, SM_BYTES>>>(x, gamma, out);
}

// round 6
// speedup vs baseline: 6.7503x; 2.0186x over previous
#include <cuda_runtime.h>
#include <cuda_bf16.h>
#include <cstdint>

#define BB 8
#define CC 256
#define TT 2048
#define RR 32

// bf16 scratch
__device__ __nv_bfloat16 g_Qb[BB*TT*RR];    // [b][t][r]
__device__ __nv_bfloat16 g_Kb[BB*TT*RR];    // [b][t][r]
__device__ __nv_bfloat16 g_Vb[BB*CC*TT];    // [b][c][t]
__device__ __nv_bfloat16 g_Xb[BB*CC*TT];    // [b][c][t]
__device__ __nv_bfloat16 g_Wb[320*CC];      // [row][c]  rows: 0-31 q, 32-63 k, 64-319 v

// ---------------------------------------------------------------------------
// PTX helpers
// ---------------------------------------------------------------------------
__device__ __forceinline__ uint32_t smaddr(const void* p) {
    return (uint32_t)__cvta_generic_to_shared(p);
}
__device__ __forceinline__ void cp16(void* dst, const void* src) {
    asm volatile("cp.async.cg.shared.global [%0], [%1], 16;"
                 :: "r"(smaddr(dst)), "l"(src) : "memory");
}
__device__ __forceinline__ void cpcommit() {
    asm volatile("cp.async.commit_group;" ::: "memory");
}
__device__ __forceinline__ void cpwait0() {
    asm volatile("cp.async.wait_group 0;" ::: "memory");
}
__device__ __forceinline__ void ldsm4(uint32_t* r, const void* p) {
    asm volatile("ldmatrix.sync.aligned.m8n8.x4.shared.b16 {%0,%1,%2,%3}, [%4];"
        : "=r"(r[0]), "=r"(r[1]), "=r"(r[2]), "=r"(r[3])
        : "r"(smaddr(p)));
}
__device__ __forceinline__ void ldsm4t(uint32_t* r, const void* p) {
    asm volatile("ldmatrix.sync.aligned.m8n8.x4.trans.shared.b16 {%0,%1,%2,%3}, [%4];"
        : "=r"(r[0]), "=r"(r[1]), "=r"(r[2]), "=r"(r[3])
        : "r"(smaddr(p)));
}
__device__ __forceinline__ void mmabf(float* d, const uint32_t* a,
                                      uint32_t b0, uint32_t b1) {
    asm volatile(
        "mma.sync.aligned.m16n8k16.row.col.f32.bf16.bf16.f32 "
        "{%0,%1,%2,%3},{%4,%5,%6,%7},{%8,%9},{%0,%1,%2,%3};"
        : "+f"(d[0]), "+f"(d[1]), "+f"(d[2]), "+f"(d[3])
        : "r"(a[0]), "r"(a[1]), "r"(a[2]), "r"(a[3]), "r"(b0), "r"(b1));
}

// ---------------------------------------------------------------------------
// Prep: x -> bf16 [b][c][t]
// ---------------------------------------------------------------------------
__global__ __launch_bounds__(256) void cvt_x_kernel(const float* __restrict__ x) {
    size_t i = ((size_t)blockIdx.x*256 + threadIdx.x)*4;
    float4 v = *reinterpret_cast<const float4*>(&x[i]);
    __nv_bfloat162 h0 = __floats2bfloat162_rn(v.x, v.y);
    __nv_bfloat162 h1 = __floats2bfloat162_rn(v.z, v.w);
    uint2 pk;
    pk.x = *reinterpret_cast<uint32_t*>(&h0);
    pk.y = *reinterpret_cast<uint32_t*>(&h1);
    *reinterpret_cast<uint2*>(&g_Xb[i]) = pk;
}

// Prep: weights -> bf16 [320][256]
__global__ __launch_bounds__(256) void cvt_w_kernel(
    const float* __restrict__ Wq, const float* __restrict__ Wk,
    const float* __restrict__ Wv) {
    int i = (blockIdx.x*256 + threadIdx.x)*4;       // 320*256 / 4 = 80 CTAs
    int row = i >> 8, col = i & 255;
    const float* src = (row < 32) ? &Wq[row*CC + col]
                     : (row < 64) ? &Wk[(row-32)*CC + col]
                                  : &Wv[(row-64)*CC + col];
    float4 v = *reinterpret_cast<const float4*>(src);
    __nv_bfloat162 h0 = __floats2bfloat162_rn(v.x, v.y);
    __nv_bfloat162 h1 = __floats2bfloat162_rn(v.z, v.w);
    uint2 pk;
    pk.x = *reinterpret_cast<uint32_t*>(&h0);
    pk.y = *reinterpret_cast<uint32_t*>(&h1);
    *reinterpret_cast<uint2*>(&g_Wb[i]) = pk;
}

// ---------------------------------------------------------------------------
// Kernel 1: projections via bf16 mma.  Grid (T/128, 5, B), 256 threads.
// CTA tile: m64 (weight rows) x n128 (t), k=256 in 4 chunks, double-buffered.
// Warp: (wm = wid>>1) m16-group, (wn = wid&1) n64-group.  B via ldmatrix.trans.
// ---------------------------------------------------------------------------
#define WST 72
#define XST 136
#define WBUF (64*WST)
#define XBUF (64*XST)
#define PROJ_SM_BYTES ((2*WBUF + 2*XBUF)*2)

__global__ __launch_bounds__(256, 2) void proj_kernel(
    const float* __restrict__ bq, const float* __restrict__ bk,
    const float* __restrict__ bv)
{
    extern __shared__ __align__(16) char smraw[];
    __nv_bfloat16* wbuf = (__nv_bfloat16*)smraw;     // [2][64][72]
    __nv_bfloat16* xbuf = wbuf + 2*WBUF;             // [2][64][136]

    const int b    = blockIdx.z;
    const int m0   = blockIdx.y * 64;
    const int n0   = blockIdx.x * 128;
    const int tid  = threadIdx.x;
    const int wid  = tid >> 5;
    const int lane = tid & 31;
    const int lq   = lane >> 2, lr = lane & 3;
    const int wm   = wid >> 1,  wn = wid & 1;
    const int l8   = (lane & 7) + ((lane & 8) ? 8 : 0);
    const int lc   = (lane >> 4) * 8;

    // prefetch k-chunk 0
    {
        #pragma unroll
        for (int j = 0; j < 2; j++) {        // W: 64x64 bf16
            int slot = tid + j*256;
            int row = slot >> 3, kc = (slot & 7)*8;
            cp16(&wbuf[row*WST + kc], &g_Wb[(m0+row)*CC + kc]);
        }
        #pragma unroll
        for (int j = 0; j < 4; j++) {        // X: 64x128 bf16
            int slot = tid + j*256;
            int row = slot >> 4, tc = (slot & 15)*8;
            cp16(&xbuf[row*XST + tc], &g_Xb[((size_t)b*CC + row)*TT + n0 + tc]);
        }
        cpcommit();
    }

    float acc[8][4];
    #pragma unroll
    for (int nf = 0; nf < 8; nf++)
        #pragma unroll
        for (int j = 0; j < 4; j++) acc[nf][j] = 0.f;

    for (int kc = 0; kc < 4; kc++) {
        const int buf = kc & 1;
        cpwait0();
        __syncthreads();

        if (kc + 1 < 4) {                    // prefetch next chunk
            const int k0 = (kc+1)*64;
            __nv_bfloat16* wd = wbuf + (buf^1)*WBUF;
            __nv_bfloat16* xd = xbuf + (buf^1)*XBUF;
            #pragma unroll
            for (int j = 0; j < 2; j++) {
                int slot = tid + j*256;
                int row = slot >> 3, kcc = (slot & 7)*8;
                cp16(&wd[row*WST + kcc], &g_Wb[(m0+row)*CC + k0 + kcc]);
            }
            #pragma unroll
            for (int j = 0; j < 4; j++) {
                int slot = tid + j*256;
                int row = slot >> 4, tc = (slot & 15)*8;
                cp16(&xd[row*XST + tc], &g_Xb[((size_t)b*CC + k0 + row)*TT + n0 + tc]);
            }
            cpcommit();
        }

        const __nv_bfloat16* wb = wbuf + buf*WBUF;
        const __nv_bfloat16* xb = xbuf + buf*XBUF;
        #pragma unroll
        for (int ks = 0; ks < 4; ks++) {
            uint32_t a[4];
            ldsm4(a, &wb[(wm*16 + l8)*WST + ks*16 + lc]);
            #pragma unroll
            for (int ng = 0; ng < 4; ng++) {
                uint32_t bx[4];
                ldsm4t(bx, &xb[(ks*16 + l8)*XST + wn*64 + ng*16 + lc]);
                mmabf(acc[ng*2+0], a, bx[0], bx[1]);
                mmabf(acc[ng*2+1], a, bx[2], bx[3]);
            }
        }
        __syncthreads();
    }

    // epilogue: bias (fp32) + bf16 store in attn-ready layouts
    const int r0 = m0 + wm*16 + lq;          // global weight row
    const int r1 = r0 + 8;
    float bias0 = (r0 < 32) ? bq[r0] : (r0 < 64) ? bk[r0-32] : bv[r0-64];
    float bias1 = (r1 < 32) ? bq[r1] : (r1 < 64) ? bk[r1-32] : bv[r1-64];

    if (m0 >= 64) {                          // V rows -> g_Vb [b][c][t]
        int v0 = r0 - 64, v1 = r1 - 64;
        #pragma unroll
        for (int nf = 0; nf < 8; nf++) {
            int col = n0 + wn*64 + nf*8 + 2*lr;
            __nv_bfloat162 h0 = __floats2bfloat162_rn(acc[nf][0] + bias0,
                                                      acc[nf][1] + bias0);
            __nv_bfloat162 h1 = __floats2bfloat162_rn(acc[nf][2] + bias1,
                                                      acc[nf][3] + bias1);
            *reinterpret_cast<__nv_bfloat162*>(&g_Vb[((size_t)b*CC + v0)*TT + col]) = h0;
            *reinterpret_cast<__nv_bfloat162*>(&g_Vb[((size_t)b*CC + v1)*TT + col]) = h1;
        }
    } else {                                 // Q/K rows -> [b][t][r]
        __nv_bfloat16* base0 = (r0 < 32) ? g_Qb : g_Kb;
        __nv_bfloat16* base1 = (r1 < 32) ? g_Qb : g_Kb;
        int rr0 = (r0 < 32) ? r0 : r0 - 32;
        int rr1 = (r1 < 32) ? r1 : r1 - 32;
        #pragma unroll
        for (int nf = 0; nf < 8; nf++) {
            int col = n0 + wn*64 + nf*8 + 2*lr;
            base0[((size_t)b*TT + col  )*RR + rr0] = __float2bfloat16(acc[nf][0] + bias0);
            base0[((size_t)b*TT + col+1)*RR + rr0] = __float2bfloat16(acc[nf][1] + bias0);
            base1[((size_t)b*TT + col  )*RR + rr1] = __float2bfloat16(acc[nf][2] + bias1);
            base1[((size_t)b*TT + col+1)*RR + rr1] = __float2bfloat16(acc[nf][3] + bias1);
        }
    }
}

// ---------------------------------------------------------------------------
// Kernel 2: flash attention (unchanged from round 4 — proven correct/fast).
// ---------------------------------------------------------------------------
#define QPH 40
#define KPH 40
#define VPH 72
#define PPH 72
#define KBUF (64*KPH)
#define VBUF (CC*VPH)
#define SM_HALVES (64*QPH + 2*KBUF + 2*VBUF + 64*PPH)
#define SM_BYTES  (SM_HALVES*2 + 2*128*4)

__global__ __launch_bounds__(256, 2) void attn_kernel(
    const float* __restrict__ x, const float* __restrict__ gamma,
    float* __restrict__ out)
{
    extern __shared__ __align__(16) char smraw[];
    __nv_bfloat16* q_s = (__nv_bfloat16*)smraw;          // [64][40]
    __nv_bfloat16* k_s = q_s + 64*QPH;                   // [2][64][40]
    __nv_bfloat16* v_s = k_s + 2*KBUF;                   // [2][256][72]
    __nv_bfloat16* p_s = v_s + 2*VBUF;                   // [64][72]
    float* ex_max = (float*)(p_s + 64*PPH);              // [8][16]
    float* ex_sum = ex_max + 128;                        // [8][16]

    const int b    = blockIdx.y;
    const int t0   = blockIdx.x * 64;
    const int tid  = threadIdx.x;
    const int wid  = tid >> 5;
    const int lane = tid & 31;
    const int lq   = lane >> 2, lr = lane & 3;
    const int mi   = wid >> 1,  ni = wid & 1;
    const int l8   = (lane & 7) + ((lane & 8) ? 8 : 0);
    const int lc   = (lane >> 4) * 8;

    {
        #pragma unroll
        for (int j = 0; j < 9; j++) {
            int slot = tid + j*256;
            if (slot < 256) {
                int row = slot >> 2, ch = slot & 3;
                cp16(&k_s[row*KPH + ch*8],
                     &g_Kb[((size_t)b*TT + row)*RR + ch*8]);
            } else {
                int vsl = slot - 256;
                int row = vsl >> 3, ch = vsl & 7;
                cp16(&v_s[row*VPH + ch*8],
                     &g_Vb[((size_t)b*CC + row)*TT + ch*8]);
            }
        }
        cpcommit();
    }

    {
        int row = tid >> 2, ch = tid & 3;
        uint4 qv = *reinterpret_cast<const uint4*>(
            &g_Qb[((size_t)b*TT + t0 + row)*RR + ch*8]);
        *reinterpret_cast<uint4*>(&q_s[row*QPH + ch*8]) = qv;
    }
    __syncthreads();
    uint32_t aq[8];
    ldsm4(aq,     &q_s[(mi*16 + l8)*QPH + lc]);
    ldsm4(aq + 4, &q_s[(mi*16 + l8)*QPH + 16 + lc]);

    float acc[16][4];
    #pragma unroll
    for (int nf = 0; nf < 16; nf++)
        #pragma unroll
        for (int j = 0; j < 4; j++) acc[nf][j] = 0.f;
    float m_prev[2] = {-1e30f, -1e30f};
    float l_run[2]  = {0.f, 0.f};

    for (int it = 0; it < TT/64; it++) {
        const int buf = it & 1;
        cpwait0();
        __syncthreads();

        if (it + 1 < TT/64) {
            const int s0 = (it+1)*64;
            __nv_bfloat16* kd = k_s + (buf^1)*KBUF;
            __nv_bfloat16* vd = v_s + (buf^1)*VBUF;
            #pragma unroll
            for (int j = 0; j < 9; j++) {
                int slot = tid + j*256;
                if (slot < 256) {
                    int row = slot >> 2, ch = slot & 3;
                    cp16(&kd[row*KPH + ch*8],
                         &g_Kb[((size_t)b*TT + s0 + row)*RR + ch*8]);
                } else {
                    int vsl = slot - 256;
                    int row = vsl >> 3, ch = vsl & 7;
                    cp16(&vd[row*VPH + ch*8],
                         &g_Vb[((size_t)b*CC + row)*TT + s0 + ch*8]);
                }
            }
            cpcommit();
        }

        const __nv_bfloat16* kb = k_s + buf*KBUF;
        float sacc[4][4];
        #pragma unroll
        for (int g = 0; g < 4; g++)
            #pragma unroll
            for (int j = 0; j < 4; j++) sacc[g][j] = 0.f;
        #pragma unroll
        for (int ks = 0; ks < 2; ks++) {
            #pragma unroll
            for (int n2 = 0; n2 < 2; n2++) {
                uint32_t kb4[4];
                ldsm4(kb4, &kb[(ni*32 + n2*16 + l8)*KPH + ks*16 + lc]);
                mmabf(sacc[n2*2+0], aq + ks*4, kb4[0], kb4[2]);
                mmabf(sacc[n2*2+1], aq + ks*4, kb4[1], kb4[3]);
            }
        }

        float mx0 = fmaxf(fmaxf(sacc[0][0], sacc[0][1]), fmaxf(sacc[1][0], sacc[1][1]));
        mx0 = fmaxf(mx0, fmaxf(fmaxf(sacc[2][0], sacc[2][1]), fmaxf(sacc[3][0], sacc[3][1])));
        float mx1 = fmaxf(fmaxf(sacc[0][2], sacc[0][3]), fmaxf(sacc[1][2], sacc[1][3]));
        mx1 = fmaxf(mx1, fmaxf(fmaxf(sacc[2][2], sacc[2][3]), fmaxf(sacc[3][2], sacc[3][3])));
        mx0 = fmaxf(mx0, __shfl_xor_sync(0xffffffffu, mx0, 1));
        mx0 = fmaxf(mx0, __shfl_xor_sync(0xffffffffu, mx0, 2));
        mx1 = fmaxf(mx1, __shfl_xor_sync(0xffffffffu, mx1, 1));
        mx1 = fmaxf(mx1, __shfl_xor_sync(0xffffffffu, mx1, 2));
        if (lr == 0) { ex_max[wid*16 + lq] = mx0; ex_max[wid*16 + 8 + lq] = mx1; }
        __syncthreads();
        mx0 = fmaxf(mx0, ex_max[(wid^1)*16 + lq]);
        mx1 = fmaxf(mx1, ex_max[(wid^1)*16 + 8 + lq]);
        float mn0 = fmaxf(m_prev[0], mx0), mn1 = fmaxf(m_prev[1], mx1);
        float al0 = __expf(m_prev[0] - mn0), al1 = __expf(m_prev[1] - mn1);
        m_prev[0] = mn0; m_prev[1] = mn1;

        float sum0 = 0.f, sum1 = 0.f;
        #pragma unroll
        for (int g = 0; g < 4; g++) {
            sacc[g][0] = __expf(sacc[g][0] - mn0);
            sacc[g][1] = __expf(sacc[g][1] - mn0);
            sacc[g][2] = __expf(sacc[g][2] - mn1);
            sacc[g][3] = __expf(sacc[g][3] - mn1);
            sum0 += sacc[g][0] + sacc[g][1];
            sum1 += sacc[g][2] + sacc[g][3];
        }
        sum0 += __shfl_xor_sync(0xffffffffu, sum0, 1);
        sum0 += __shfl_xor_sync(0xffffffffu, sum0, 2);
        sum1 += __shfl_xor_sync(0xffffffffu, sum1, 1);
        sum1 += __shfl_xor_sync(0xffffffffu, sum1, 2);
        if (lr == 0) { ex_sum[wid*16 + lq] = sum0; ex_sum[wid*16 + 8 + lq] = sum1; }

        #pragma unroll
        for (int g = 0; g < 4; g++) {
            int cb = ni*32 + g*8 + 2*lr;
            __nv_bfloat162 plo = __floats2bfloat162_rn(sacc[g][0], sacc[g][1]);
            __nv_bfloat162 phi = __floats2bfloat162_rn(sacc[g][2], sacc[g][3]);
            *reinterpret_cast<__nv_bfloat162*>(&p_s[(mi*16 + lq)*PPH + cb])     = plo;
            *reinterpret_cast<__nv_bfloat162*>(&p_s[(mi*16 + 8 + lq)*PPH + cb]) = phi;
        }
        #pragma unroll
        for (int nf = 0; nf < 16; nf++) {
            acc[nf][0] *= al0; acc[nf][1] *= al0;
            acc[nf][2] *= al1; acc[nf][3] *= al1;
        }
        __syncthreads();
        l_run[0] = l_run[0]*al0 + sum0 + ex_sum[(wid^1)*16 + lq];
        l_run[1] = l_run[1]*al1 + sum1 + ex_sum[(wid^1)*16 + 8 + lq];

        const __nv_bfloat16* vb = v_s + buf*VBUF;
        #pragma unroll
        for (int ks = 0; ks < 4; ks++) {
            uint32_t pa[4];
            ldsm4(pa, &p_s[(mi*16 + l8)*PPH + ks*16 + lc]);
            #pragma unroll
            for (int cg = 0; cg < 8; cg++) {
                uint32_t vb4[4];
                ldsm4(vb4, &vb[(ni*128 + cg*16 + l8)*VPH + ks*16 + lc]);
                mmabf(acc[cg*2+0], pa, vb4[0], vb4[2]);
                mmabf(acc[cg*2+1], pa, vb4[1], vb4[3]);
            }
        }
    }

    const float gm   = gamma[0];
    const float inv0 = 1.0f / l_run[0];
    const float inv1 = 1.0f / l_run[1];
    const int   trow = t0 + mi*16 + lq;
    #pragma unroll
    for (int nf = 0; nf < 16; nf++) {
        int c = ni*128 + (nf >> 1)*16 + (nf & 1)*8 + 2*lr;
        size_t i0 = ((size_t)(b*CC + c))*TT + trow;
        out[i0      ] = x[i0      ] + gm*acc[nf][0]*inv0;
        out[i0 + TT ] = x[i0 + TT ] + gm*acc[nf][1]*inv0;
        out[i0 + 8  ] = x[i0 + 8  ] + gm*acc[nf][2]*inv1;
        out[i0+TT+8 ] = x[i0+TT+8 ] + gm*acc[nf][3]*inv1;
    }
}

// ---------------------------------------------------------------------------
extern "C" void kernel_launch(void* const* d_in, const int* in_sizes, int n_in,
                              void* d_out, int out_size) {
    const float* x     = (const float*)d_in[0];
    const float* Wq    = (const float*)d_in[1];
    const float* bq    = (const float*)d_in[2];
    const float* Wk    = (const float*)d_in[3];
    const float* bk    = (const float*)d_in[4];
    const float* Wv    = (const float*)d_in[5];
    const float* bv    = (const float*)d_in[6];
    const float* gamma = (const float*)d_in[7];
    float* out = (float*)d_out;

    (void)in_sizes; (void)n_in; (void)out_size;

    cudaFuncSetAttribute(proj_kernel, cudaFuncAttributeMaxDynamicSharedMemorySize,
                         PROJ_SM_BYTES);
    cudaFuncSetAttribute(attn_kernel, cudaFuncAttributeMaxDynamicSharedMemorySize,
                         SM_BYTES);

    cvt_x_kernel<<<BB*CC*TT/1024, 256>>>(x);
    cvt_w_kernel<<<320*CC/1024, 256>>>(Wq, Wk, Wv);

    dim3 g1(TT/128, 5, BB);
    proj_kernel<<<g1, 256, PROJ_SM_BYTES>>>(bq, bk, bv);

    dim3 g2(TT/64, BB);
    attn_kernel<<<g2, 256, SM_BYTES>>>(x, gamma, out);
}